// round 1
// baseline (speedup 1.0000x reference)
#include <cuda_runtime.h>
#include <math.h>

#define SQ   2048
#define DIM  768
#define NH   12
#define HD   64
#define QKVD 2304
#define FFD  384
#define MAXN 128

// ---------------- scratch (device globals; no allocation allowed) ----------------
__device__ float g_xin[SQ * DIM];     // LN0(exp+pert)
__device__ float g_qkv[SQ * QKVD];    // qkv projection
__device__ float g_att[SQ * DIM];     // attention output
__device__ float g_prj[SQ * DIM];     // out projection
__device__ float g_x1 [SQ * DIM];     // LN1(prj + xin)
__device__ float g_hh [SQ * FFD];     // relu(x1 w1^T + b1)
__device__ float g_ff [SQ * DIM];     // hh w2^T + b2
__device__ int   g_nbr[SQ * MAXN];
__device__ int   g_cnt[SQ];

// ---------------- block reduce ----------------
__device__ __forceinline__ float block_sum(float v, float* sh) {
    #pragma unroll
    for (int o = 16; o > 0; o >>= 1) v += __shfl_down_sync(0xffffffffu, v, o);
    if ((threadIdx.x & 31) == 0) sh[threadIdx.x >> 5] = v;
    __syncthreads();
    if (threadIdx.x < 32) {
        float t = (threadIdx.x < 8) ? sh[threadIdx.x] : 0.f;
        #pragma unroll
        for (int o = 4; o > 0; o >>= 1) t += __shfl_down_sync(0xffffffffu, t, o);
        if (threadIdx.x == 0) sh[0] = t;
    }
    __syncthreads();
    float r = sh[0];
    __syncthreads();
    return r;
}

// ---------------- fused (a+b) -> LayerNorm ----------------
__global__ void add_ln_kernel(const float* __restrict__ a, const float* __restrict__ b,
                              const float* __restrict__ g, const float* __restrict__ be,
                              float* __restrict__ out) {
    __shared__ float sh[8];
    int row = blockIdx.x;
    const float* pa = a + (size_t)row * DIM;
    const float* pb = b + (size_t)row * DIM;
    float v[3]; float s = 0.f;
    #pragma unroll
    for (int i = 0; i < 3; i++) { int c = threadIdx.x + i * 256; v[i] = pa[c] + pb[c]; s += v[i]; }
    float mu = block_sum(s, sh) * (1.f / DIM);
    float s2 = 0.f;
    #pragma unroll
    for (int i = 0; i < 3; i++) { float d = v[i] - mu; s2 += d * d; }
    float var = block_sum(s2, sh) * (1.f / DIM);
    float rstd = rsqrtf(var + 1e-5f);
    float* po = out + (size_t)row * DIM;
    #pragma unroll
    for (int i = 0; i < 3; i++) {
        int c = threadIdx.x + i * 256;
        po[c] = (v[i] - mu) * rstd * g[c] + be[c];
    }
}

// ---------------- adjacency -> per-query neighbor lists ----------------
__global__ void build_nbr_kernel(const int* __restrict__ adj) {
    int q = blockIdx.x;
    __shared__ int cnt;
    if (threadIdx.x == 0) cnt = 0;
    __syncthreads();
    for (int k = threadIdx.x; k < SQ; k += blockDim.x) {
        if (adj[(size_t)q * SQ + k] != 0) {
            int p = atomicAdd(&cnt, 1);
            if (p < MAXN) g_nbr[q * MAXN + p] = k;
        }
    }
    __syncthreads();
    if (threadIdx.x == 0) g_cnt[q] = cnt < MAXN ? cnt : MAXN;
}

// ---------------- sparse attention: 1 block per query, 12 heads x 16 lanes ----------------
__global__ void attn_kernel() {
    int q   = blockIdx.x;
    int tid = threadIdx.x;          // 192 threads
    int h   = tid >> 4;             // head 0..11
    int l   = tid & 15;             // lane-in-head 0..15 (4 dims each)
    __shared__ float qv[DIM];
    __shared__ float sc[NH][MAXN];
    __shared__ int   nbr[MAXN];

    int n = g_cnt[q];
    for (int i = tid; i < DIM; i += 192) qv[i] = g_qkv[(size_t)q * QKVD + i];
    for (int i = tid; i < n;   i += 192) nbr[i] = g_nbr[q * MAXN + i];
    __syncthreads();

    // scores
    const float4 q4 = *(const float4*)(qv + h * HD + l * 4);
    for (int j = 0; j < n; j++) {
        const float4 k4 = *(const float4*)(g_qkv + (size_t)nbr[j] * QKVD + DIM + h * HD + l * 4);
        float s = q4.x * k4.x + q4.y * k4.y + q4.z * k4.z + q4.w * k4.w;
        #pragma unroll
        for (int o = 8; o > 0; o >>= 1) s += __shfl_down_sync(0xffffffffu, s, o, 16);
        if (l == 0) sc[h][j] = s * 0.125f;   // 1/sqrt(64)
    }
    __syncwarp();

    // softmax over neighbors (per head, 16 lanes)
    float m = -INFINITY;
    for (int j = l; j < n; j += 16) m = fmaxf(m, sc[h][j]);
    #pragma unroll
    for (int o = 8; o > 0; o >>= 1) m = fmaxf(m, __shfl_xor_sync(0xffffffffu, m, o, 16));
    float sum = 0.f;
    for (int j = l; j < n; j += 16) { float e = __expf(sc[h][j] - m); sc[h][j] = e; sum += e; }
    #pragma unroll
    for (int o = 8; o > 0; o >>= 1) sum += __shfl_xor_sync(0xffffffffu, sum, o, 16);
    float inv = 1.f / sum;
    __syncwarp();

    // weighted V accumulation
    float4 acc = make_float4(0.f, 0.f, 0.f, 0.f);
    for (int j = 0; j < n; j++) {
        float p = sc[h][j] * inv;
        const float4 v4 = *(const float4*)(g_qkv + (size_t)nbr[j] * QKVD + 2 * DIM + h * HD + l * 4);
        acc.x += p * v4.x; acc.y += p * v4.y; acc.z += p * v4.z; acc.w += p * v4.w;
    }
    *(float4*)(g_att + (size_t)q * DIM + h * HD + l * 4) = acc;
}

// ---------------- C[M,N] = A[M,K] * B[N,K]^T + bias (optional ReLU) ----------------
// 128x128 block tile, BK=8, 256 threads, 8x8 per thread.
template <bool RELU>
__global__ void __launch_bounds__(256, 2)
gemm_nt_kernel(const float* __restrict__ A, const float* __restrict__ B,
               const float* __restrict__ bias, float* __restrict__ C,
               int M, int N, int K) {
    __shared__ float As[8][128];
    __shared__ float Bs[8][128];
    int bm = blockIdx.y, bn = blockIdx.x;
    int tid = threadIdx.x;
    int r  = tid >> 1;
    int kk = (tid & 1) * 4;
    int ty = tid >> 4, tx = tid & 15;

    const float* Ap = A + ((size_t)bm * 128 + r) * K + kk;
    const float* Bp = B + ((size_t)bn * 128 + r) * K + kk;

    float acc[8][8];
    #pragma unroll
    for (int i = 0; i < 8; i++)
        #pragma unroll
        for (int j = 0; j < 8; j++) acc[i][j] = 0.f;

    for (int kt = 0; kt < K; kt += 8) {
        float4 a4 = *(const float4*)(Ap + kt);
        float4 b4 = *(const float4*)(Bp + kt);
        __syncthreads();
        As[kk + 0][r] = a4.x; As[kk + 1][r] = a4.y; As[kk + 2][r] = a4.z; As[kk + 3][r] = a4.w;
        Bs[kk + 0][r] = b4.x; Bs[kk + 1][r] = b4.y; Bs[kk + 2][r] = b4.z; Bs[kk + 3][r] = b4.w;
        __syncthreads();
        #pragma unroll
        for (int k = 0; k < 8; k++) {
            float ar[8], br[8];
            #pragma unroll
            for (int i = 0; i < 8; i++) ar[i] = As[k][ty * 8 + i];
            #pragma unroll
            for (int j = 0; j < 8; j++) br[j] = Bs[k][tx * 8 + j];
            #pragma unroll
            for (int i = 0; i < 8; i++)
                #pragma unroll
                for (int j = 0; j < 8; j++) acc[i][j] = fmaf(ar[i], br[j], acc[i][j]);
        }
    }

    #pragma unroll
    for (int i = 0; i < 8; i++) {
        int mrow = bm * 128 + ty * 8 + i;
        #pragma unroll
        for (int j = 0; j < 8; j++) {
            int ncol = bn * 128 + tx * 8 + j;
            float v = acc[i][j] + bias[ncol];
            if (RELU) v = fmaxf(v, 0.f);
            C[(size_t)mrow * N + ncol] = v;
        }
    }
}

// ---------------- launch ----------------
extern "C" void kernel_launch(void* const* d_in, const int* in_sizes, int n_in,
                              void* d_out, int out_size) {
    const float* exp_e = (const float*)d_in[0];
    const float* per_e = (const float*)d_in[1];
    const float* ipw   = (const float*)d_in[2];
    const float* ipb   = (const float*)d_in[3];
    const float* opw   = (const float*)d_in[4];
    const float* opb   = (const float*)d_in[5];
    const float* ln0g  = (const float*)d_in[6];
    const float* ln0b  = (const float*)d_in[7];
    const float* ln1g  = (const float*)d_in[8];
    const float* ln1b  = (const float*)d_in[9];
    const float* ln2g  = (const float*)d_in[10];
    const float* ln2b  = (const float*)d_in[11];
    const float* w1    = (const float*)d_in[12];
    const float* b1    = (const float*)d_in[13];
    const float* w2    = (const float*)d_in[14];
    const float* b2    = (const float*)d_in[15];
    const int*   adj   = (const int*)d_in[16];
    float* out = (float*)d_out;

    float *xin, *qkv, *att, *prj, *x1, *hh, *ff;
    cudaGetSymbolAddress((void**)&xin, g_xin);
    cudaGetSymbolAddress((void**)&qkv, g_qkv);
    cudaGetSymbolAddress((void**)&att, g_att);
    cudaGetSymbolAddress((void**)&prj, g_prj);
    cudaGetSymbolAddress((void**)&x1,  g_x1);
    cudaGetSymbolAddress((void**)&hh,  g_hh);
    cudaGetSymbolAddress((void**)&ff,  g_ff);

    // 1. x_in = LN0(exp + pert)
    add_ln_kernel<<<SQ, 256>>>(exp_e, per_e, ln0g, ln0b, xin);
    // 2. adjacency -> neighbor lists (independent of step 1)
    build_nbr_kernel<<<SQ, 256>>>(adj);
    // 3. qkv = x_in @ in_proj_w^T + in_proj_b
    gemm_nt_kernel<false><<<dim3(QKVD / 128, SQ / 128), 256>>>(xin, ipw, ipb, qkv, SQ, QKVD, DIM);
    // 4. sparse masked attention
    attn_kernel<<<SQ, 192>>>();
    // 5. out projection
    gemm_nt_kernel<false><<<dim3(DIM / 128, SQ / 128), 256>>>(att, opw, opb, prj, SQ, DIM, DIM);
    // 6. x1 = LN1(prj + x_in)
    add_ln_kernel<<<SQ, 256>>>(prj, xin, ln1g, ln1b, x1);
    // 7. hh = relu(x1 @ w1^T + b1)
    gemm_nt_kernel<true><<<dim3(FFD / 128, SQ / 128), 256>>>(x1, w1, b1, hh, SQ, FFD, DIM);
    // 8. ff = hh @ w2^T + b2
    gemm_nt_kernel<false><<<dim3(DIM / 128, SQ / 128), 256>>>(hh, w2, b2, ff, SQ, DIM, FFD);
    // 9. out = LN2(x1 + ff)
    add_ln_kernel<<<SQ, 256>>>(x1, ff, ln2g, ln2b, out);
}

// round 3
// speedup vs baseline: 2.3626x; 2.3626x over previous
#include <cuda_runtime.h>
#include <cuda_bf16.h>
#include <cstdint>
#include <math.h>

#define SQ   2048
#define DIM  768
#define NH   12
#define HD   64
#define QKVD 2304
#define FFD  384
#define MAXN 128

// ---------------- scratch (device globals; no allocation allowed) ----------------
__device__ float g_xin[SQ * DIM];
__device__ float g_qkv[SQ * QKVD];
__device__ float g_prj[SQ * DIM];
__device__ float g_x1 [SQ * DIM];
__device__ float g_ff [SQ * DIM];
__device__ int   g_nbr[SQ * MAXN];
__device__ int   g_cnt[SQ];

__device__ __nv_bfloat16 g_xin_h[SQ * DIM],  g_xin_l[SQ * DIM];
__device__ __nv_bfloat16 g_x1_h [SQ * DIM],  g_x1_l [SQ * DIM];
__device__ __nv_bfloat16 g_att_h[SQ * DIM],  g_att_l[SQ * DIM];
__device__ __nv_bfloat16 g_hh_h [SQ * FFD],  g_hh_l [SQ * FFD];
__device__ __nv_bfloat16 g_wq_h [QKVD * DIM], g_wq_l[QKVD * DIM];
__device__ __nv_bfloat16 g_wo_h [DIM * DIM],  g_wo_l[DIM * DIM];
__device__ __nv_bfloat16 g_w1_h [FFD * DIM],  g_w1_l[FFD * DIM];
__device__ __nv_bfloat16 g_w2_h [DIM * FFD],  g_w2_l[DIM * FFD];

// ---------------- PTX helpers (sm_80-era only: safe for compute_103 target) -------
__device__ __forceinline__ uint32_t smem_u32(const void* p) {
    uint32_t a;
    asm("{ .reg .u64 t; cvta.to.shared.u64 t, %1; cvt.u32.u64 %0, t; }" : "=r"(a) : "l"(p));
    return a;
}
#define CP_ASYNC16(dst, src) \
    asm volatile("cp.async.cg.shared.global [%0], [%1], 16;" :: "r"(dst), "l"(src))
#define CP_COMMIT() asm volatile("cp.async.commit_group;" ::: "memory")
#define CP_WAIT(n)  asm volatile("cp.async.wait_group %0;" :: "n"(n) : "memory")

__device__ __forceinline__ void ldsm_x4(uint32_t (&r)[4], uint32_t addr) {
    asm volatile("ldmatrix.sync.aligned.m8n8.x4.shared.b16 {%0,%1,%2,%3}, [%4];"
                 : "=r"(r[0]), "=r"(r[1]), "=r"(r[2]), "=r"(r[3]) : "r"(addr));
}
__device__ __forceinline__ void ldsm_x2(uint32_t (&r)[2], uint32_t addr) {
    asm volatile("ldmatrix.sync.aligned.m8n8.x2.shared.b16 {%0,%1}, [%2];"
                 : "=r"(r[0]), "=r"(r[1]) : "r"(addr));
}
__device__ __forceinline__ void mma_bf16(float (&d)[4], const uint32_t (&a)[4],
                                         const uint32_t (&b)[2]) {
    asm volatile("mma.sync.aligned.m16n8k16.row.col.f32.bf16.bf16.f32 "
                 "{%0,%1,%2,%3}, {%4,%5,%6,%7}, {%8,%9}, {%0,%1,%2,%3};"
                 : "+f"(d[0]), "+f"(d[1]), "+f"(d[2]), "+f"(d[3])
                 : "r"(a[0]), "r"(a[1]), "r"(a[2]), "r"(a[3]), "r"(b[0]), "r"(b[1]));
}

__device__ __forceinline__ void split1(float v, __nv_bfloat16& h, __nv_bfloat16& l) {
    h = __float2bfloat16(v);
    l = __float2bfloat16(v - __bfloat162float(h));
}

// ---------------- block reduce ----------------
__device__ __forceinline__ float block_sum(float v, float* sh) {
    #pragma unroll
    for (int o = 16; o > 0; o >>= 1) v += __shfl_down_sync(0xffffffffu, v, o);
    if ((threadIdx.x & 31) == 0) sh[threadIdx.x >> 5] = v;
    __syncthreads();
    if (threadIdx.x < 32) {
        float t = (threadIdx.x < 8) ? sh[threadIdx.x] : 0.f;
        #pragma unroll
        for (int o = 4; o > 0; o >>= 1) t += __shfl_down_sync(0xffffffffu, t, o);
        if (threadIdx.x == 0) sh[0] = t;
    }
    __syncthreads();
    float r = sh[0];
    __syncthreads();
    return r;
}

// ---------------- fused (a+b) -> LayerNorm (+ optional bf16 split out) ----------------
__global__ void add_ln_kernel(const float* __restrict__ a, const float* __restrict__ b,
                              const float* __restrict__ g, const float* __restrict__ be,
                              float* __restrict__ out,
                              __nv_bfloat16* __restrict__ ohi, __nv_bfloat16* __restrict__ olo) {
    __shared__ float sh[8];
    int row = blockIdx.x;
    const float* pa = a + (size_t)row * DIM;
    const float* pb = b + (size_t)row * DIM;
    float v[3]; float s = 0.f;
    #pragma unroll
    for (int i = 0; i < 3; i++) { int c = threadIdx.x + i * 256; v[i] = pa[c] + pb[c]; s += v[i]; }
    float mu = block_sum(s, sh) * (1.f / DIM);
    float s2 = 0.f;
    #pragma unroll
    for (int i = 0; i < 3; i++) { float d = v[i] - mu; s2 += d * d; }
    float var = block_sum(s2, sh) * (1.f / DIM);
    float rstd = rsqrtf(var + 1e-5f);
    #pragma unroll
    for (int i = 0; i < 3; i++) {
        int c = threadIdx.x + i * 256;
        float y = (v[i] - mu) * rstd * g[c] + be[c];
        out[(size_t)row * DIM + c] = y;
        if (ohi) {
            __nv_bfloat16 h, l; split1(y, h, l);
            ohi[(size_t)row * DIM + c] = h;
            olo[(size_t)row * DIM + c] = l;
        }
    }
}

// ---------------- fp32 -> bf16 split ----------------
__global__ void split_kernel(const float* __restrict__ x, __nv_bfloat16* __restrict__ hi,
                             __nv_bfloat16* __restrict__ lo, int n4) {
    int i = blockIdx.x * 256 + threadIdx.x;
    if (i < n4) {
        float4 v = ((const float4*)x)[i];
        __nv_bfloat16 h0, l0, h1, l1, h2, l2, h3, l3;
        split1(v.x, h0, l0); split1(v.y, h1, l1); split1(v.z, h2, l2); split1(v.w, h3, l3);
        __nv_bfloat162* ph = (__nv_bfloat162*)(hi + (size_t)i * 4);
        __nv_bfloat162* pl = (__nv_bfloat162*)(lo + (size_t)i * 4);
        ph[0] = __nv_bfloat162(h0, h1); ph[1] = __nv_bfloat162(h2, h3);
        pl[0] = __nv_bfloat162(l0, l1); pl[1] = __nv_bfloat162(l2, l3);
    }
}

// ---------------- adjacency -> per-query neighbor lists ----------------
__global__ void build_nbr_kernel(const int* __restrict__ adj) {
    int q = blockIdx.x;
    __shared__ int cnt;
    if (threadIdx.x == 0) cnt = 0;
    __syncthreads();
    for (int k = threadIdx.x; k < SQ; k += blockDim.x) {
        if (adj[(size_t)q * SQ + k] != 0) {
            int p = atomicAdd(&cnt, 1);
            if (p < MAXN) g_nbr[q * MAXN + p] = k;
        }
    }
    __syncthreads();
    if (threadIdx.x == 0) g_cnt[q] = cnt < MAXN ? cnt : MAXN;
}

// ---------------- sparse attention (writes bf16-split output) ----------------
__global__ void attn_kernel() {
    int q    = blockIdx.x;
    int tid  = threadIdx.x;          // 192 threads
    int head = tid >> 4;
    int l    = tid & 15;
    __shared__ float qv[DIM];
    __shared__ float sc[NH][MAXN];
    __shared__ int   nbr[MAXN];

    int n = g_cnt[q];
    for (int i = tid; i < DIM; i += 192) qv[i] = g_qkv[(size_t)q * QKVD + i];
    for (int i = tid; i < n;   i += 192) nbr[i] = g_nbr[q * MAXN + i];
    __syncthreads();

    const float4 q4 = *(const float4*)(qv + head * HD + l * 4);
    for (int j = 0; j < n; j++) {
        const float4 k4 = *(const float4*)(g_qkv + (size_t)nbr[j] * QKVD + DIM + head * HD + l * 4);
        float s = q4.x * k4.x + q4.y * k4.y + q4.z * k4.z + q4.w * k4.w;
        #pragma unroll
        for (int o = 8; o > 0; o >>= 1) s += __shfl_down_sync(0xffffffffu, s, o, 16);
        if (l == 0) sc[head][j] = s * 0.125f;
    }
    __syncwarp();

    float m = -INFINITY;
    for (int j = l; j < n; j += 16) m = fmaxf(m, sc[head][j]);
    #pragma unroll
    for (int o = 8; o > 0; o >>= 1) m = fmaxf(m, __shfl_xor_sync(0xffffffffu, m, o, 16));
    float sum = 0.f;
    for (int j = l; j < n; j += 16) { float e = __expf(sc[head][j] - m); sc[head][j] = e; sum += e; }
    #pragma unroll
    for (int o = 8; o > 0; o >>= 1) sum += __shfl_xor_sync(0xffffffffu, sum, o, 16);
    float inv = 1.f / sum;
    __syncwarp();

    float4 acc = make_float4(0.f, 0.f, 0.f, 0.f);
    for (int j = 0; j < n; j++) {
        float p = sc[head][j] * inv;
        const float4 v4 = *(const float4*)(g_qkv + (size_t)nbr[j] * QKVD + 2 * DIM + head * HD + l * 4);
        acc.x += p * v4.x; acc.y += p * v4.y; acc.z += p * v4.z; acc.w += p * v4.w;
    }
    size_t base = (size_t)q * DIM + head * HD + l * 4;
    __nv_bfloat16 h0, l0, h1, l1, h2, l2, h3, l3;
    split1(acc.x, h0, l0); split1(acc.y, h1, l1); split1(acc.z, h2, l2); split1(acc.w, h3, l3);
    __nv_bfloat162* ph = (__nv_bfloat162*)(g_att_h + base);
    __nv_bfloat162* pl = (__nv_bfloat162*)(g_att_l + base);
    ph[0] = __nv_bfloat162(h0, h1); ph[1] = __nv_bfloat162(h2, h3);
    pl[0] = __nv_bfloat162(l0, l1); pl[1] = __nv_bfloat162(l2, l3);
}

// ---------------- bf16-split GEMM via mma.sync: C = A*B^T + bias ----------------
// 128x128 tile, BK=32, 256 threads (2x4 warps, each 64x32).
// 3 HMMA products per tile-step: Ahi*Bhi + Ahi*Blo + Alo*Bhi, fp32 accum.
#define RSB    80                    // padded row stride bytes (40 bf16): conflict-free
#define MATB   (128 * RSB)           // 10240 bytes per operand matrix per stage
#define STAGEB (4 * MATB)            // Ahi, Alo, Bhi, Blo
#define GEMM_SMEM (2 * STAGEB)       // 81920

template <bool RELU, bool BF16OUT>
__global__ void __launch_bounds__(256, 1)
gemm_mma(const __nv_bfloat16* __restrict__ Ahi, const __nv_bfloat16* __restrict__ Alo,
         const __nv_bfloat16* __restrict__ Bhi, const __nv_bfloat16* __restrict__ Blo,
         const float* __restrict__ bias,
         float* __restrict__ C, __nv_bfloat16* __restrict__ Chi, __nv_bfloat16* __restrict__ Clo,
         int N, int K) {
    extern __shared__ char dsm[];
    const uint32_t sb = smem_u32(dsm);

    const int tid = threadIdx.x, wid = tid >> 5, lane = tid & 31;
    const int bm = blockIdx.y, bn = blockIdx.x;
    const int wm = wid >> 2, wn = wid & 3;          // 2 x 4 warp grid
    const int m0 = wm * 64, n0 = wn * 32;

    const __nv_bfloat16* gp[4] = {
        Ahi + (size_t)(bm * 128) * K, Alo + (size_t)(bm * 128) * K,
        Bhi + (size_t)(bn * 128) * K, Blo + (size_t)(bn * 128) * K };

    const int ldrow = tid >> 2, ldc16 = tid & 3;    // each thread: 1 chunk/matrix/half

    float acc[4][4][4];
    #pragma unroll
    for (int i = 0; i < 4; i++)
        #pragma unroll
        for (int j = 0; j < 4; j++)
            #pragma unroll
            for (int v = 0; v < 4; v++) acc[i][j][v] = 0.f;

    const int KT = K >> 5;

    // stage loader: 4 matrices x 128 rows x 64B ; 256 threads -> 2 chunks per matrix
    auto load_stage = [&](int s, int kt) {
        uint32_t base = sb + s * STAGEB;
        #pragma unroll
        for (int m = 0; m < 4; m++) {
            const __nv_bfloat16* g = gp[m] + kt * 32;
            #pragma unroll
            for (int j = 0; j < 2; j++) {
                int row = ldrow + j * 64;
                CP_ASYNC16(base + m * MATB + row * RSB + ldc16 * 16,
                           g + (size_t)row * K + ldc16 * 8);
            }
        }
        CP_COMMIT();
    };

    load_stage(0, 0);

    const int arow = lane & 15, ahalf = lane >> 4;
    const int brow = lane & 7,  bhalf = (lane >> 3) & 1;

    for (int kt = 0; kt < KT; kt++) {
        if (kt + 1 < KT) { load_stage((kt + 1) & 1, kt + 1); CP_WAIT(1); }
        else             { CP_WAIT(0); }
        __syncthreads();

        uint32_t base = sb + (kt & 1) * STAGEB;
        #pragma unroll
        for (int ks = 0; ks < 2; ks++) {
            uint32_t ah[4][4], al[4][4], bh[4][2], bl[4][2];
            #pragma unroll
            for (int im = 0; im < 4; im++) {
                uint32_t off = (m0 + im * 16 + arow) * RSB + ks * 32 + ahalf * 16;
                ldsm_x4(ah[im], base + 0 * MATB + off);
                ldsm_x4(al[im], base + 1 * MATB + off);
            }
            #pragma unroll
            for (int in = 0; in < 4; in++) {
                uint32_t off = (n0 + in * 8 + brow) * RSB + ks * 32 + bhalf * 16;
                ldsm_x2(bh[in], base + 2 * MATB + off);
                ldsm_x2(bl[in], base + 3 * MATB + off);
            }
            #pragma unroll
            for (int im = 0; im < 4; im++)
                #pragma unroll
                for (int in = 0; in < 4; in++) {
                    mma_bf16(acc[im][in], ah[im], bh[in]);
                    mma_bf16(acc[im][in], ah[im], bl[in]);
                    mma_bf16(acc[im][in], al[im], bh[in]);
                }
        }
        __syncthreads();
    }

    // epilogue: registers -> gmem directly
    const int crow = lane >> 2, ccol = (lane & 3) * 2;
    #pragma unroll
    for (int im = 0; im < 4; im++) {
        #pragma unroll
        for (int in = 0; in < 4; in++) {
            int col = bn * 128 + n0 + in * 8 + ccol;
            float b0 = bias[col], b1 = bias[col + 1];
            #pragma unroll
            for (int half = 0; half < 2; half++) {
                int row = bm * 128 + m0 + im * 16 + crow + half * 8;
                float v0 = acc[im][in][half * 2 + 0] + b0;
                float v1 = acc[im][in][half * 2 + 1] + b1;
                if (RELU) { v0 = fmaxf(v0, 0.f); v1 = fmaxf(v1, 0.f); }
                size_t go = (size_t)row * N + col;
                if (BF16OUT) {
                    __nv_bfloat16 h0, l0, h1, l1;
                    split1(v0, h0, l0); split1(v1, h1, l1);
                    *(__nv_bfloat162*)(Chi + go) = __nv_bfloat162(h0, h1);
                    *(__nv_bfloat162*)(Clo + go) = __nv_bfloat162(l0, l1);
                } else {
                    *(float2*)(C + go) = make_float2(v0, v1);
                }
            }
        }
    }
}

// ---------------- launch ----------------
extern "C" void kernel_launch(void* const* d_in, const int* in_sizes, int n_in,
                              void* d_out, int out_size) {
    const float* exp_e = (const float*)d_in[0];
    const float* per_e = (const float*)d_in[1];
    const float* ipw   = (const float*)d_in[2];
    const float* ipb   = (const float*)d_in[3];
    const float* opw   = (const float*)d_in[4];
    const float* opb   = (const float*)d_in[5];
    const float* ln0g  = (const float*)d_in[6];
    const float* ln0b  = (const float*)d_in[7];
    const float* ln1g  = (const float*)d_in[8];
    const float* ln1b  = (const float*)d_in[9];
    const float* ln2g  = (const float*)d_in[10];
    const float* ln2b  = (const float*)d_in[11];
    const float* w1    = (const float*)d_in[12];
    const float* b1    = (const float*)d_in[13];
    const float* w2    = (const float*)d_in[14];
    const float* b2    = (const float*)d_in[15];
    const int*   adj   = (const int*)d_in[16];
    float* out = (float*)d_out;

    float *xin, *qkv, *prj, *x1, *ff;
    cudaGetSymbolAddress((void**)&xin, g_xin);
    cudaGetSymbolAddress((void**)&qkv, g_qkv);
    cudaGetSymbolAddress((void**)&prj, g_prj);
    cudaGetSymbolAddress((void**)&x1,  g_x1);
    cudaGetSymbolAddress((void**)&ff,  g_ff);
    __nv_bfloat16 *xinh, *xinl, *x1h, *x1l, *atth, *attl, *hhh, *hhl;
    __nv_bfloat16 *wqh, *wql, *woh, *wol, *w1h, *w1l, *w2h, *w2l;
    cudaGetSymbolAddress((void**)&xinh, g_xin_h); cudaGetSymbolAddress((void**)&xinl, g_xin_l);
    cudaGetSymbolAddress((void**)&x1h,  g_x1_h);  cudaGetSymbolAddress((void**)&x1l,  g_x1_l);
    cudaGetSymbolAddress((void**)&atth, g_att_h); cudaGetSymbolAddress((void**)&attl, g_att_l);
    cudaGetSymbolAddress((void**)&hhh,  g_hh_h);  cudaGetSymbolAddress((void**)&hhl,  g_hh_l);
    cudaGetSymbolAddress((void**)&wqh,  g_wq_h);  cudaGetSymbolAddress((void**)&wql,  g_wq_l);
    cudaGetSymbolAddress((void**)&woh,  g_wo_h);  cudaGetSymbolAddress((void**)&wol,  g_wo_l);
    cudaGetSymbolAddress((void**)&w1h,  g_w1_h);  cudaGetSymbolAddress((void**)&w1l,  g_w1_l);
    cudaGetSymbolAddress((void**)&w2h,  g_w2_h);  cudaGetSymbolAddress((void**)&w2l,  g_w2_l);

    cudaFuncSetAttribute(gemm_mma<false, false>, cudaFuncAttributeMaxDynamicSharedMemorySize, GEMM_SMEM);
    cudaFuncSetAttribute(gemm_mma<true,  true >, cudaFuncAttributeMaxDynamicSharedMemorySize, GEMM_SMEM);

    // weight splits (independent)
    split_kernel<<<(QKVD * DIM / 4 + 255) / 256, 256>>>(ipw, wqh, wql, QKVD * DIM / 4);
    split_kernel<<<(DIM * DIM / 4 + 255) / 256, 256>>>(opw, woh, wol, DIM * DIM / 4);
    split_kernel<<<(FFD * DIM / 4 + 255) / 256, 256>>>(w1, w1h, w1l, FFD * DIM / 4);
    split_kernel<<<(DIM * FFD / 4 + 255) / 256, 256>>>(w2, w2h, w2l, DIM * FFD / 4);
    // neighbor lists
    build_nbr_kernel<<<SQ, 256>>>(adj);
    // x_in = LN0(exp + pert), + bf16 split
    add_ln_kernel<<<SQ, 256>>>(exp_e, per_e, ln0g, ln0b, xin, xinh, xinl);
    // qkv = x_in @ ipw^T + ipb
    gemm_mma<false, false><<<dim3(QKVD / 128, SQ / 128), 256, GEMM_SMEM>>>(
        xinh, xinl, wqh, wql, ipb, qkv, nullptr, nullptr, QKVD, DIM);
    // sparse attention -> bf16 split att
    attn_kernel<<<SQ, 192>>>();
    // prj = att @ opw^T + opb
    gemm_mma<false, false><<<dim3(DIM / 128, SQ / 128), 256, GEMM_SMEM>>>(
        atth, attl, woh, wol, opb, prj, nullptr, nullptr, DIM, DIM);
    // x1 = LN1(prj + xin), + split
    add_ln_kernel<<<SQ, 256>>>(prj, xin, ln1g, ln1b, x1, x1h, x1l);
    // hh = relu(x1 @ w1^T + b1) -> bf16 split only
    gemm_mma<true, true><<<dim3(FFD / 128, SQ / 128), 256, GEMM_SMEM>>>(
        x1h, x1l, w1h, w1l, b1, nullptr, hhh, hhl, FFD, DIM);
    // ff = hh @ w2^T + b2
    gemm_mma<false, false><<<dim3(DIM / 128, SQ / 128), 256, GEMM_SMEM>>>(
        hhh, hhl, w2h, w2l, b2, ff, nullptr, nullptr, DIM, FFD);
    // out = LN2(x1 + ff)
    add_ln_kernel<<<SQ, 256>>>(x1, ff, ln2g, ln2b, out, nullptr, nullptr);
}

// round 4
// speedup vs baseline: 2.7459x; 1.1622x over previous
#include <cuda_runtime.h>
#include <cuda_bf16.h>
#include <cstdint>
#include <math.h>

#define SQ   2048
#define DIM  768
#define NH   12
#define HD   64
#define QKVD 2304
#define FFD  384
#define MAXN 128

// ---------------- scratch (device globals; no allocation allowed) ----------------
__device__ float g_xin[SQ * DIM];
__device__ float g_qkv[SQ * QKVD];
__device__ float g_prj[SQ * DIM];
__device__ float g_x1 [SQ * DIM];
__device__ float g_ff [SQ * DIM];
__device__ int   g_nbr[SQ * MAXN];
__device__ int   g_cnt[SQ];

__device__ __nv_bfloat16 g_xin_h[SQ * DIM],  g_xin_l[SQ * DIM];
__device__ __nv_bfloat16 g_x1_h [SQ * DIM],  g_x1_l [SQ * DIM];
__device__ __nv_bfloat16 g_att_h[SQ * DIM],  g_att_l[SQ * DIM];
__device__ __nv_bfloat16 g_hh_h [SQ * FFD],  g_hh_l [SQ * FFD];
__device__ __nv_bfloat16 g_wq_h [QKVD * DIM], g_wq_l[QKVD * DIM];
__device__ __nv_bfloat16 g_wo_h [DIM * DIM],  g_wo_l[DIM * DIM];
__device__ __nv_bfloat16 g_w1_h [FFD * DIM],  g_w1_l[FFD * DIM];
__device__ __nv_bfloat16 g_w2_h [DIM * FFD],  g_w2_l[DIM * FFD];

// ---------------- PTX helpers (sm_80-era only: safe for compute_103 target) -------
__device__ __forceinline__ uint32_t smem_u32(const void* p) {
    uint32_t a;
    asm("{ .reg .u64 t; cvta.to.shared.u64 t, %1; cvt.u32.u64 %0, t; }" : "=r"(a) : "l"(p));
    return a;
}
#define CP_ASYNC16(dst, src) \
    asm volatile("cp.async.cg.shared.global [%0], [%1], 16;" :: "r"(dst), "l"(src))
#define CP_COMMIT() asm volatile("cp.async.commit_group;" ::: "memory")
#define CP_WAIT(n)  asm volatile("cp.async.wait_group %0;" :: "n"(n) : "memory")

__device__ __forceinline__ void ldsm_x4(uint32_t (&r)[4], uint32_t addr) {
    asm volatile("ldmatrix.sync.aligned.m8n8.x4.shared.b16 {%0,%1,%2,%3}, [%4];"
                 : "=r"(r[0]), "=r"(r[1]), "=r"(r[2]), "=r"(r[3]) : "r"(addr));
}
__device__ __forceinline__ void ldsm_x2(uint32_t (&r)[2], uint32_t addr) {
    asm volatile("ldmatrix.sync.aligned.m8n8.x2.shared.b16 {%0,%1}, [%2];"
                 : "=r"(r[0]), "=r"(r[1]) : "r"(addr));
}
__device__ __forceinline__ void mma_bf16(float (&d)[4], const uint32_t (&a)[4],
                                         const uint32_t (&b)[2]) {
    asm volatile("mma.sync.aligned.m16n8k16.row.col.f32.bf16.bf16.f32 "
                 "{%0,%1,%2,%3}, {%4,%5,%6,%7}, {%8,%9}, {%0,%1,%2,%3};"
                 : "+f"(d[0]), "+f"(d[1]), "+f"(d[2]), "+f"(d[3])
                 : "r"(a[0]), "r"(a[1]), "r"(a[2]), "r"(a[3]), "r"(b[0]), "r"(b[1]));
}

__device__ __forceinline__ void split1(float v, __nv_bfloat16& h, __nv_bfloat16& l) {
    h = __float2bfloat16(v);
    l = __float2bfloat16(v - __bfloat162float(h));
}

// ---------------- block reduce ----------------
__device__ __forceinline__ float block_sum(float v, float* sh) {
    #pragma unroll
    for (int o = 16; o > 0; o >>= 1) v += __shfl_down_sync(0xffffffffu, v, o);
    if ((threadIdx.x & 31) == 0) sh[threadIdx.x >> 5] = v;
    __syncthreads();
    if (threadIdx.x < 32) {
        float t = (threadIdx.x < 8) ? sh[threadIdx.x] : 0.f;
        #pragma unroll
        for (int o = 4; o > 0; o >>= 1) t += __shfl_down_sync(0xffffffffu, t, o);
        if (threadIdx.x == 0) sh[0] = t;
    }
    __syncthreads();
    float r = sh[0];
    __syncthreads();
    return r;
}

// ---------------- fused (a+b) -> LayerNorm (+ optional bf16 split out) ----------------
__global__ void add_ln_kernel(const float* __restrict__ a, const float* __restrict__ b,
                              const float* __restrict__ g, const float* __restrict__ be,
                              float* __restrict__ out,
                              __nv_bfloat16* __restrict__ ohi, __nv_bfloat16* __restrict__ olo) {
    __shared__ float sh[8];
    int row = blockIdx.x;
    const float* pa = a + (size_t)row * DIM;
    const float* pb = b + (size_t)row * DIM;
    float v[3]; float s = 0.f;
    #pragma unroll
    for (int i = 0; i < 3; i++) { int c = threadIdx.x + i * 256; v[i] = pa[c] + pb[c]; s += v[i]; }
    float mu = block_sum(s, sh) * (1.f / DIM);
    float s2 = 0.f;
    #pragma unroll
    for (int i = 0; i < 3; i++) { float d = v[i] - mu; s2 += d * d; }
    float var = block_sum(s2, sh) * (1.f / DIM);
    float rstd = rsqrtf(var + 1e-5f);
    #pragma unroll
    for (int i = 0; i < 3; i++) {
        int c = threadIdx.x + i * 256;
        float y = (v[i] - mu) * rstd * g[c] + be[c];
        out[(size_t)row * DIM + c] = y;
        if (ohi) {
            __nv_bfloat16 h, l; split1(y, h, l);
            ohi[(size_t)row * DIM + c] = h;
            olo[(size_t)row * DIM + c] = l;
        }
    }
}

// ---------------- fused fp32 -> bf16 split for 4 weight matrices ----------------
__global__ void split4_kernel(const float* __restrict__ s0, __nv_bfloat16* h0, __nv_bfloat16* l0, int n0,
                              const float* __restrict__ s1, __nv_bfloat16* h1, __nv_bfloat16* l1, int n1,
                              const float* __restrict__ s2, __nv_bfloat16* h2, __nv_bfloat16* l2, int n2,
                              const float* __restrict__ s3, __nv_bfloat16* h3, __nv_bfloat16* l3, int n3) {
    const float* x; __nv_bfloat16 *hi, *lo; int n4;
    switch (blockIdx.y) {
        case 0: x = s0; hi = h0; lo = l0; n4 = n0; break;
        case 1: x = s1; hi = h1; lo = l1; n4 = n1; break;
        case 2: x = s2; hi = h2; lo = l2; n4 = n2; break;
        default: x = s3; hi = h3; lo = l3; n4 = n3; break;
    }
    int i = blockIdx.x * 256 + threadIdx.x;
    if (i < n4) {
        float4 v = ((const float4*)x)[i];
        __nv_bfloat16 a0, b0, a1, b1, a2, b2, a3, b3;
        split1(v.x, a0, b0); split1(v.y, a1, b1); split1(v.z, a2, b2); split1(v.w, a3, b3);
        __nv_bfloat162* ph = (__nv_bfloat162*)(hi + (size_t)i * 4);
        __nv_bfloat162* pl = (__nv_bfloat162*)(lo + (size_t)i * 4);
        ph[0] = __nv_bfloat162(a0, a1); ph[1] = __nv_bfloat162(a2, a3);
        pl[0] = __nv_bfloat162(b0, b1); pl[1] = __nv_bfloat162(b2, b3);
    }
}

// ---------------- adjacency -> per-query neighbor lists ----------------
__global__ void build_nbr_kernel(const int* __restrict__ adj) {
    int q = blockIdx.x;
    __shared__ int cnt;
    if (threadIdx.x == 0) cnt = 0;
    __syncthreads();
    for (int k = threadIdx.x; k < SQ; k += blockDim.x) {
        if (adj[(size_t)q * SQ + k] != 0) {
            int p = atomicAdd(&cnt, 1);
            if (p < MAXN) g_nbr[q * MAXN + p] = k;
        }
    }
    __syncthreads();
    if (threadIdx.x == 0) g_cnt[q] = cnt < MAXN ? cnt : MAXN;
}

// ---------------- sparse attention (writes bf16-split output) ----------------
__global__ void attn_kernel() {
    int q    = blockIdx.x;
    int tid  = threadIdx.x;          // 192 threads
    int head = tid >> 4;
    int l    = tid & 15;
    __shared__ float qv[DIM];
    __shared__ float sc[NH][MAXN];
    __shared__ int   nbr[MAXN];

    int n = g_cnt[q];
    for (int i = tid; i < DIM; i += 192) qv[i] = g_qkv[(size_t)q * QKVD + i];
    for (int i = tid; i < n;   i += 192) nbr[i] = g_nbr[q * MAXN + i];
    __syncthreads();

    const float4 q4 = *(const float4*)(qv + head * HD + l * 4);
    const size_t koff = DIM + head * HD + l * 4;
    int j = 0;
    for (; j + 1 < n; j += 2) {
        const float4 ka = *(const float4*)(g_qkv + (size_t)nbr[j]     * QKVD + koff);
        const float4 kb = *(const float4*)(g_qkv + (size_t)nbr[j + 1] * QKVD + koff);
        float sa = q4.x * ka.x + q4.y * ka.y + q4.z * ka.z + q4.w * ka.w;
        float sb = q4.x * kb.x + q4.y * kb.y + q4.z * kb.z + q4.w * kb.w;
        #pragma unroll
        for (int o = 8; o > 0; o >>= 1) {
            sa += __shfl_down_sync(0xffffffffu, sa, o, 16);
            sb += __shfl_down_sync(0xffffffffu, sb, o, 16);
        }
        if (l == 0) { sc[head][j] = sa * 0.125f; sc[head][j + 1] = sb * 0.125f; }
    }
    if (j < n) {
        const float4 ka = *(const float4*)(g_qkv + (size_t)nbr[j] * QKVD + koff);
        float sa = q4.x * ka.x + q4.y * ka.y + q4.z * ka.z + q4.w * ka.w;
        #pragma unroll
        for (int o = 8; o > 0; o >>= 1) sa += __shfl_down_sync(0xffffffffu, sa, o, 16);
        if (l == 0) sc[head][j] = sa * 0.125f;
    }
    __syncwarp();

    float m = -INFINITY;
    for (int i = l; i < n; i += 16) m = fmaxf(m, sc[head][i]);
    #pragma unroll
    for (int o = 8; o > 0; o >>= 1) m = fmaxf(m, __shfl_xor_sync(0xffffffffu, m, o, 16));
    float sum = 0.f;
    for (int i = l; i < n; i += 16) { float e = __expf(sc[head][i] - m); sc[head][i] = e; sum += e; }
    #pragma unroll
    for (int o = 8; o > 0; o >>= 1) sum += __shfl_xor_sync(0xffffffffu, sum, o, 16);
    float inv = 1.f / sum;
    __syncwarp();

    const size_t voff = 2 * DIM + head * HD + l * 4;
    float4 acc0 = make_float4(0.f, 0.f, 0.f, 0.f);
    float4 acc1 = make_float4(0.f, 0.f, 0.f, 0.f);
    j = 0;
    for (; j + 1 < n; j += 2) {
        float pa = sc[head][j] * inv, pb = sc[head][j + 1] * inv;
        const float4 va = *(const float4*)(g_qkv + (size_t)nbr[j]     * QKVD + voff);
        const float4 vb = *(const float4*)(g_qkv + (size_t)nbr[j + 1] * QKVD + voff);
        acc0.x += pa * va.x; acc0.y += pa * va.y; acc0.z += pa * va.z; acc0.w += pa * va.w;
        acc1.x += pb * vb.x; acc1.y += pb * vb.y; acc1.z += pb * vb.z; acc1.w += pb * vb.w;
    }
    if (j < n) {
        float pa = sc[head][j] * inv;
        const float4 va = *(const float4*)(g_qkv + (size_t)nbr[j] * QKVD + voff);
        acc0.x += pa * va.x; acc0.y += pa * va.y; acc0.z += pa * va.z; acc0.w += pa * va.w;
    }
    acc0.x += acc1.x; acc0.y += acc1.y; acc0.z += acc1.z; acc0.w += acc1.w;

    size_t base = (size_t)q * DIM + head * HD + l * 4;
    __nv_bfloat16 h0, l0, h1, l1, h2, l2, h3, l3;
    split1(acc0.x, h0, l0); split1(acc0.y, h1, l1); split1(acc0.z, h2, l2); split1(acc0.w, h3, l3);
    __nv_bfloat162* ph = (__nv_bfloat162*)(g_att_h + base);
    __nv_bfloat162* pl = (__nv_bfloat162*)(g_att_l + base);
    ph[0] = __nv_bfloat162(h0, h1); ph[1] = __nv_bfloat162(h2, h3);
    pl[0] = __nv_bfloat162(l0, l1); pl[1] = __nv_bfloat162(l2, l3);
}

// ---------------- bf16-split GEMM via mma.sync: C = A*B^T + bias ----------------
#define RSB    80                    // padded row stride bytes: conflict-free ldmatrix
#define MATB   (128 * RSB)
#define STAGEB (4 * MATB)
#define GEMM_SMEM (2 * STAGEB)       // 81920

template <bool RELU, bool BF16OUT>
__global__ void __launch_bounds__(256, 1)
gemm_mma(const __nv_bfloat16* __restrict__ Ahi, const __nv_bfloat16* __restrict__ Alo,
         const __nv_bfloat16* __restrict__ Bhi, const __nv_bfloat16* __restrict__ Blo,
         const float* __restrict__ bias,
         float* __restrict__ C, __nv_bfloat16* __restrict__ Chi, __nv_bfloat16* __restrict__ Clo,
         int N, int K) {
    extern __shared__ char dsm[];
    const uint32_t sb = smem_u32(dsm);

    const int tid = threadIdx.x, wid = tid >> 5, lane = tid & 31;
    const int bm = blockIdx.y, bn = blockIdx.x;
    const int wm = wid >> 2, wn = wid & 3;
    const int m0 = wm * 64, n0 = wn * 32;

    const __nv_bfloat16* gp[4] = {
        Ahi + (size_t)(bm * 128) * K, Alo + (size_t)(bm * 128) * K,
        Bhi + (size_t)(bn * 128) * K, Blo + (size_t)(bn * 128) * K };

    const int ldrow = tid >> 2, ldc16 = tid & 3;

    float acc[4][4][4];
    #pragma unroll
    for (int i = 0; i < 4; i++)
        #pragma unroll
        for (int j = 0; j < 4; j++)
            #pragma unroll
            for (int v = 0; v < 4; v++) acc[i][j][v] = 0.f;

    const int KT = K >> 5;

    auto load_stage = [&](int s, int kt) {
        uint32_t base = sb + s * STAGEB;
        #pragma unroll
        for (int m = 0; m < 4; m++) {
            const __nv_bfloat16* g = gp[m] + kt * 32;
            #pragma unroll
            for (int j = 0; j < 2; j++) {
                int row = ldrow + j * 64;
                CP_ASYNC16(base + m * MATB + row * RSB + ldc16 * 16,
                           g + (size_t)row * K + ldc16 * 8);
            }
        }
        CP_COMMIT();
    };

    load_stage(0, 0);

    const int arow = lane & 15, ahalf = lane >> 4;
    const int brow = lane & 7,  bhalf = (lane >> 3) & 1;

    for (int kt = 0; kt < KT; kt++) {
        if (kt + 1 < KT) { load_stage((kt + 1) & 1, kt + 1); CP_WAIT(1); }
        else             { CP_WAIT(0); }
        __syncthreads();

        uint32_t base = sb + (kt & 1) * STAGEB;
        #pragma unroll
        for (int ks = 0; ks < 2; ks++) {
            uint32_t ah[4][4], al[4][4], bh[4][2], bl[4][2];
            #pragma unroll
            for (int im = 0; im < 4; im++) {
                uint32_t off = (m0 + im * 16 + arow) * RSB + ks * 32 + ahalf * 16;
                ldsm_x4(ah[im], base + 0 * MATB + off);
                ldsm_x4(al[im], base + 1 * MATB + off);
            }
            #pragma unroll
            for (int in = 0; in < 4; in++) {
                uint32_t off = (n0 + in * 8 + brow) * RSB + ks * 32 + bhalf * 16;
                ldsm_x2(bh[in], base + 2 * MATB + off);
                ldsm_x2(bl[in], base + 3 * MATB + off);
            }
            #pragma unroll
            for (int im = 0; im < 4; im++)
                #pragma unroll
                for (int in = 0; in < 4; in++) {
                    mma_bf16(acc[im][in], ah[im], bh[in]);
                    mma_bf16(acc[im][in], ah[im], bl[in]);
                    mma_bf16(acc[im][in], al[im], bh[in]);
                }
        }
        __syncthreads();
    }

    const int crow = lane >> 2, ccol = (lane & 3) * 2;
    #pragma unroll
    for (int im = 0; im < 4; im++) {
        #pragma unroll
        for (int in = 0; in < 4; in++) {
            int col = bn * 128 + n0 + in * 8 + ccol;
            float b0 = bias[col], b1 = bias[col + 1];
            #pragma unroll
            for (int half = 0; half < 2; half++) {
                int row = bm * 128 + m0 + im * 16 + crow + half * 8;
                float v0 = acc[im][in][half * 2 + 0] + b0;
                float v1 = acc[im][in][half * 2 + 1] + b1;
                if (RELU) { v0 = fmaxf(v0, 0.f); v1 = fmaxf(v1, 0.f); }
                size_t go = (size_t)row * N + col;
                if (BF16OUT) {
                    __nv_bfloat16 h0, l0, h1, l1;
                    split1(v0, h0, l0); split1(v1, h1, l1);
                    *(__nv_bfloat162*)(Chi + go) = __nv_bfloat162(h0, h1);
                    *(__nv_bfloat162*)(Clo + go) = __nv_bfloat162(l0, l1);
                } else {
                    *(float2*)(C + go) = make_float2(v0, v1);
                }
            }
        }
    }
}

// ---------------- 64x64-tile variant (128 threads, 2x2 warps of 32x32) ----------------
#define MATB64   (64 * RSB)          // 5120
#define STAGEB64 (4 * MATB64)        // 20480
#define GEMM_SMEM64 (2 * STAGEB64)   // 40960 (fits default smem)

template <bool RELU, bool BF16OUT>
__global__ void __launch_bounds__(128, 4)
gemm_mma64(const __nv_bfloat16* __restrict__ Ahi, const __nv_bfloat16* __restrict__ Alo,
           const __nv_bfloat16* __restrict__ Bhi, const __nv_bfloat16* __restrict__ Blo,
           const float* __restrict__ bias,
           float* __restrict__ C, __nv_bfloat16* __restrict__ Chi, __nv_bfloat16* __restrict__ Clo,
           int N, int K) {
    extern __shared__ char dsm[];
    const uint32_t sb = smem_u32(dsm);

    const int tid = threadIdx.x, wid = tid >> 5, lane = tid & 31;
    const int bm = blockIdx.y, bn = blockIdx.x;
    const int wm = wid >> 1, wn = wid & 1;
    const int m0 = wm * 32, n0 = wn * 32;

    const __nv_bfloat16* gp[4] = {
        Ahi + (size_t)(bm * 64) * K, Alo + (size_t)(bm * 64) * K,
        Bhi + (size_t)(bn * 64) * K, Blo + (size_t)(bn * 64) * K };

    const int ldrow = tid >> 2, ldc16 = tid & 3;

    float acc[2][4][4];
    #pragma unroll
    for (int i = 0; i < 2; i++)
        #pragma unroll
        for (int j = 0; j < 4; j++)
            #pragma unroll
            for (int v = 0; v < 4; v++) acc[i][j][v] = 0.f;

    const int KT = K >> 5;

    auto load_stage = [&](int s, int kt) {
        uint32_t base = sb + s * STAGEB64;
        #pragma unroll
        for (int m = 0; m < 4; m++) {
            const __nv_bfloat16* g = gp[m] + kt * 32;
            #pragma unroll
            for (int j = 0; j < 2; j++) {
                int row = ldrow + j * 32;
                CP_ASYNC16(base + m * MATB64 + row * RSB + ldc16 * 16,
                           g + (size_t)row * K + ldc16 * 8);
            }
        }
        CP_COMMIT();
    };

    load_stage(0, 0);

    const int arow = lane & 15, ahalf = lane >> 4;
    const int brow = lane & 7,  bhalf = (lane >> 3) & 1;

    for (int kt = 0; kt < KT; kt++) {
        if (kt + 1 < KT) { load_stage((kt + 1) & 1, kt + 1); CP_WAIT(1); }
        else             { CP_WAIT(0); }
        __syncthreads();

        uint32_t base = sb + (kt & 1) * STAGEB64;
        #pragma unroll
        for (int ks = 0; ks < 2; ks++) {
            uint32_t ah[2][4], al[2][4], bh[4][2], bl[4][2];
            #pragma unroll
            for (int im = 0; im < 2; im++) {
                uint32_t off = (m0 + im * 16 + arow) * RSB + ks * 32 + ahalf * 16;
                ldsm_x4(ah[im], base + 0 * MATB64 + off);
                ldsm_x4(al[im], base + 1 * MATB64 + off);
            }
            #pragma unroll
            for (int in = 0; in < 4; in++) {
                uint32_t off = (n0 + in * 8 + brow) * RSB + ks * 32 + bhalf * 16;
                ldsm_x2(bh[in], base + 2 * MATB64 + off);
                ldsm_x2(bl[in], base + 3 * MATB64 + off);
            }
            #pragma unroll
            for (int im = 0; im < 2; im++)
                #pragma unroll
                for (int in = 0; in < 4; in++) {
                    mma_bf16(acc[im][in], ah[im], bh[in]);
                    mma_bf16(acc[im][in], ah[im], bl[in]);
                    mma_bf16(acc[im][in], al[im], bh[in]);
                }
        }
        __syncthreads();
    }

    const int crow = lane >> 2, ccol = (lane & 3) * 2;
    #pragma unroll
    for (int im = 0; im < 2; im++) {
        #pragma unroll
        for (int in = 0; in < 4; in++) {
            int col = bn * 64 + n0 + in * 8 + ccol;
            float b0 = bias[col], b1 = bias[col + 1];
            #pragma unroll
            for (int half = 0; half < 2; half++) {
                int row = bm * 64 + m0 + im * 16 + crow + half * 8;
                float v0 = acc[im][in][half * 2 + 0] + b0;
                float v1 = acc[im][in][half * 2 + 1] + b1;
                if (RELU) { v0 = fmaxf(v0, 0.f); v1 = fmaxf(v1, 0.f); }
                size_t go = (size_t)row * N + col;
                if (BF16OUT) {
                    __nv_bfloat16 h0, l0, h1, l1;
                    split1(v0, h0, l0); split1(v1, h1, l1);
                    *(__nv_bfloat162*)(Chi + go) = __nv_bfloat162(h0, h1);
                    *(__nv_bfloat162*)(Clo + go) = __nv_bfloat162(l0, l1);
                } else {
                    *(float2*)(C + go) = make_float2(v0, v1);
                }
            }
        }
    }
}

// ---------------- launch ----------------
extern "C" void kernel_launch(void* const* d_in, const int* in_sizes, int n_in,
                              void* d_out, int out_size) {
    const float* exp_e = (const float*)d_in[0];
    const float* per_e = (const float*)d_in[1];
    const float* ipw   = (const float*)d_in[2];
    const float* ipb   = (const float*)d_in[3];
    const float* opw   = (const float*)d_in[4];
    const float* opb   = (const float*)d_in[5];
    const float* ln0g  = (const float*)d_in[6];
    const float* ln0b  = (const float*)d_in[7];
    const float* ln1g  = (const float*)d_in[8];
    const float* ln1b  = (const float*)d_in[9];
    const float* ln2g  = (const float*)d_in[10];
    const float* ln2b  = (const float*)d_in[11];
    const float* w1    = (const float*)d_in[12];
    const float* b1    = (const float*)d_in[13];
    const float* w2    = (const float*)d_in[14];
    const float* b2    = (const float*)d_in[15];
    const int*   adj   = (const int*)d_in[16];
    float* out = (float*)d_out;

    float *xin, *qkv, *prj, *x1, *ff;
    cudaGetSymbolAddress((void**)&xin, g_xin);
    cudaGetSymbolAddress((void**)&qkv, g_qkv);
    cudaGetSymbolAddress((void**)&prj, g_prj);
    cudaGetSymbolAddress((void**)&x1,  g_x1);
    cudaGetSymbolAddress((void**)&ff,  g_ff);
    __nv_bfloat16 *xinh, *xinl, *x1h, *x1l, *atth, *attl, *hhh, *hhl;
    __nv_bfloat16 *wqh, *wql, *woh, *wol, *w1h, *w1l, *w2h, *w2l;
    cudaGetSymbolAddress((void**)&xinh, g_xin_h); cudaGetSymbolAddress((void**)&xinl, g_xin_l);
    cudaGetSymbolAddress((void**)&x1h,  g_x1_h);  cudaGetSymbolAddress((void**)&x1l,  g_x1_l);
    cudaGetSymbolAddress((void**)&atth, g_att_h); cudaGetSymbolAddress((void**)&attl, g_att_l);
    cudaGetSymbolAddress((void**)&hhh,  g_hh_h);  cudaGetSymbolAddress((void**)&hhl,  g_hh_l);
    cudaGetSymbolAddress((void**)&wqh,  g_wq_h);  cudaGetSymbolAddress((void**)&wql,  g_wq_l);
    cudaGetSymbolAddress((void**)&woh,  g_wo_h);  cudaGetSymbolAddress((void**)&wol,  g_wo_l);
    cudaGetSymbolAddress((void**)&w1h,  g_w1_h);  cudaGetSymbolAddress((void**)&w1l,  g_w1_l);
    cudaGetSymbolAddress((void**)&w2h,  g_w2_h);  cudaGetSymbolAddress((void**)&w2l,  g_w2_l);

    cudaFuncSetAttribute(gemm_mma<false, false>, cudaFuncAttributeMaxDynamicSharedMemorySize, GEMM_SMEM);

    // all four weight splits in one launch
    split4_kernel<<<dim3(1728, 4), 256>>>(
        ipw, wqh, wql, QKVD * DIM / 4,
        opw, woh, wol, DIM * DIM / 4,
        w1,  w1h, w1l, FFD * DIM / 4,
        w2,  w2h, w2l, DIM * FFD / 4);
    // neighbor lists
    build_nbr_kernel<<<SQ, 256>>>(adj);
    // x_in = LN0(exp + pert), + bf16 split
    add_ln_kernel<<<SQ, 256>>>(exp_e, per_e, ln0g, ln0b, xin, xinh, xinl);
    // qkv = x_in @ ipw^T + ipb   (288 CTAs, 128x128)
    gemm_mma<false, false><<<dim3(QKVD / 128, SQ / 128), 256, GEMM_SMEM>>>(
        xinh, xinl, wqh, wql, ipb, qkv, nullptr, nullptr, QKVD, DIM);
    // sparse attention -> bf16 split att
    attn_kernel<<<SQ, 192>>>();
    // prj = att @ opw^T + opb   (384 CTAs, 64x64)
    gemm_mma64<false, false><<<dim3(DIM / 64, SQ / 64), 128, GEMM_SMEM64>>>(
        atth, attl, woh, wol, opb, prj, nullptr, nullptr, DIM, DIM);
    // x1 = LN1(prj + xin), + split
    add_ln_kernel<<<SQ, 256>>>(prj, xin, ln1g, ln1b, x1, x1h, x1l);
    // hh = relu(x1 @ w1^T + b1) -> bf16 split   (192 CTAs, 64x64)
    gemm_mma64<true, true><<<dim3(FFD / 64, SQ / 64), 128, GEMM_SMEM64>>>(
        x1h, x1l, w1h, w1l, b1, nullptr, hhh, hhl, FFD, DIM);
    // ff = hh @ w2^T + b2   (384 CTAs, 64x64)
    gemm_mma64<false, false><<<dim3(DIM / 64, SQ / 64), 128, GEMM_SMEM64>>>(
        hhh, hhl, w2h, w2l, b2, ff, nullptr, nullptr, DIM, FFD);
    // out = LN2(x1 + ff)
    add_ln_kernel<<<SQ, 256>>>(x1, ff, ln2g, ln2b, out, nullptr, nullptr);
}